// round 1
// baseline (speedup 1.0000x reference)
#include <cuda_runtime.h>
#include <math.h>

// Problem constants
#define NN   50000
#define EE   800000
#define DIN  64
#define HIDD 128
#define DOUTC 64
#define BB   2

// ---------------- scratch (static device globals; no allocation) ----------------
__device__ float g_h [NN * 128];     // projected features for current layer
__device__ float g_el[NN * 2];       // per-node attention left  (max 2 heads)
__device__ float g_er[NN * 2];       // per-node attention right
__device__ float g_y1[NN * 128];     // layer1 output
__device__ float g_y2[NN * 128];     // layer2 output
__device__ int   g_rowptr[NN + 1];   // CSR by dst
__device__ int   g_cursor[NN];       // degree / scatter cursor
__device__ int   g_csrc [EE];        // src per CSR slot

// ---------------- CSR build ----------------
__global__ void zero_deg_kernel() {
    int i = blockIdx.x * blockDim.x + threadIdx.x;
    if (i < NN) g_cursor[i] = 0;
}

__global__ void hist_kernel(const int* __restrict__ dst) {
    int e = blockIdx.x * blockDim.x + threadIdx.x;
    if (e < EE) atomicAdd(&g_cursor[dst[e]], 1);
}

// Single-block scan over 50k degrees; writes exclusive prefix into both
// g_rowptr (persistent) and g_cursor (consumed by scatter).
__global__ void scan_kernel() {
    __shared__ int ss[1024];
    const int t  = threadIdx.x;
    const int CH = (NN + 1023) / 1024;          // 49
    const int b  = t * CH;
    const int e  = min(b + CH, NN);
    int s = 0;
    for (int i = b; i < e; i++) s += g_cursor[i];
    ss[t] = s;
    __syncthreads();
    for (int off = 1; off < 1024; off <<= 1) {
        int v = (t >= off) ? ss[t - off] : 0;
        __syncthreads();
        ss[t] += v;
        __syncthreads();
    }
    int run = (t == 0) ? 0 : ss[t - 1];
    for (int i = b; i < e; i++) {
        int d = g_cursor[i];
        g_rowptr[i] = run;
        g_cursor[i] = run;
        run += d;
    }
    if (t == 1023) g_rowptr[NN] = ss[1023];
}

__global__ void scatter_kernel(const int* __restrict__ src, const int* __restrict__ dst) {
    int e = blockIdx.x * blockDim.x + threadIdx.x;
    if (e < EE) {
        int p = atomicAdd(&g_cursor[dst[e]], 1);
        g_csrc[p] = src[e];
    }
}

// ---------------- GEMM + attention coefficients ----------------
// One warp per node-row. Computes h = x@W, el = sum(h*al) per head, er likewise.
template <int K, int HD, int H>
__global__ __launch_bounds__(128) void gemm_att_kernel(
    const float* __restrict__ x, const float* __restrict__ W,
    const float* __restrict__ al, const float* __restrict__ ar,
    float* __restrict__ hout, float* __restrict__ el, float* __restrict__ er)
{
    constexpr int VW  = HD / 32;   // features per lane (4 or 2)
    constexpr int LPH = 32 / H;    // lanes per head

    __shared__ float sx[4][K];
    const int warp = threadIdx.x >> 5;
    const int lane = threadIdx.x & 31;
    const int row  = blockIdx.x * 4 + warp;
    if (row >= NN) return;

    const float* xr = x + (size_t)row * K;
    #pragma unroll
    for (int i = lane; i < K; i += 32) sx[warp][i] = xr[i];
    __syncwarp();

    float acc[VW];
    #pragma unroll
    for (int j = 0; j < VW; j++) acc[j] = 0.f;
    const int c0 = lane * VW;

    #pragma unroll 4
    for (int k = 0; k < K; k++) {
        const float xk = sx[warp][k];
        if constexpr (VW == 4) {
            float4 wv = *reinterpret_cast<const float4*>(W + (size_t)k * HD + c0);
            acc[0] = fmaf(xk, wv.x, acc[0]);
            acc[1] = fmaf(xk, wv.y, acc[1]);
            acc[2] = fmaf(xk, wv.z, acc[2]);
            acc[3] = fmaf(xk, wv.w, acc[3]);
        } else {
            float2 wv = *reinterpret_cast<const float2*>(W + (size_t)k * HD + c0);
            acc[0] = fmaf(xk, wv.x, acc[0]);
            acc[1] = fmaf(xk, wv.y, acc[1]);
        }
    }

    if constexpr (VW == 4) {
        float4 o = make_float4(acc[0], acc[1], acc[2], acc[3]);
        *reinterpret_cast<float4*>(hout + (size_t)row * HD + c0) = o;
    } else {
        float2 o = make_float2(acc[0], acc[1]);
        *reinterpret_cast<float2*>(hout + (size_t)row * HD + c0) = o;
    }

    float pel = 0.f, per_ = 0.f;
    #pragma unroll
    for (int j = 0; j < VW; j++) {
        pel  = fmaf(acc[j], al[c0 + j], pel);
        per_ = fmaf(acc[j], ar[c0 + j], per_);
    }
    #pragma unroll
    for (int off = LPH >> 1; off > 0; off >>= 1) {
        pel  += __shfl_xor_sync(0xffffffffu, pel,  off);
        per_ += __shfl_xor_sync(0xffffffffu, per_, off);
    }
    if ((lane & (LPH - 1)) == 0) {
        int hh = lane / LPH;
        el[row * H + hh] = pel;
        er[row * H + hh] = per_;
    }
}

// ---------------- fused edge-softmax + aggregation ----------------
// One warp per destination node. No max-subtraction (exact identity), no atomics.
template <int HD, int H, bool RELU>
__global__ __launch_bounds__(256) void aggregate_kernel(
    const float* __restrict__ hbuf, const float* __restrict__ el,
    const float* __restrict__ er, const float* __restrict__ bias,
    float* __restrict__ out)
{
    constexpr int VW = HD / 32;
    constexpr int D  = HD / H;

    const int gw   = (blockIdx.x * blockDim.x + threadIdx.x) >> 5;
    const int lane = threadIdx.x & 31;
    if (gw >= NN) return;

    const int s0 = g_rowptr[gw];
    const int s1 = g_rowptr[gw + 1];
    const int c0 = lane * VW;
    const int hl = c0 / D;  // this lane's head (0 when H==1)

    const float er_own = er[gw * H + hl];

    float acc[VW];
    #pragma unroll
    for (int j = 0; j < VW; j++) acc[j] = 0.f;
    float ssum = 0.f;

    int srcn = (s0 < s1) ? g_csrc[s0] : 0;
    for (int e = s0; e < s1; e++) {
        const int src = srcn;
        if (e + 1 < s1) srcn = g_csrc[e + 1];   // prefetch next src index

        float v = el[src * H + hl] + er_own;
        v = (v > 0.f) ? v : 0.2f * v;
        const float w = __expf(v);
        ssum += w;

        const float* hr = hbuf + (size_t)src * HD + c0;
        if constexpr (VW == 4) {
            float4 hv = *reinterpret_cast<const float4*>(hr);
            acc[0] = fmaf(w, hv.x, acc[0]);
            acc[1] = fmaf(w, hv.y, acc[1]);
            acc[2] = fmaf(w, hv.z, acc[2]);
            acc[3] = fmaf(w, hv.w, acc[3]);
        } else {
            float2 hv = *reinterpret_cast<const float2*>(hr);
            acc[0] = fmaf(w, hv.x, acc[0]);
            acc[1] = fmaf(w, hv.y, acc[1]);
        }
    }

    float outv[VW];
    if (s1 > s0) {
        const float inv = 1.f / ssum;
        #pragma unroll
        for (int j = 0; j < VW; j++) outv[j] = fmaf(acc[j], inv, bias[c0 + j]);
    } else {
        #pragma unroll
        for (int j = 0; j < VW; j++) outv[j] = bias[c0 + j];
    }
    if (RELU) {
        #pragma unroll
        for (int j = 0; j < VW; j++) outv[j] = fmaxf(outv[j], 0.f);
    }

    if constexpr (VW == 4) {
        float4 o = make_float4(outv[0], outv[1], outv[2], outv[3]);
        *reinterpret_cast<float4*>(out + (size_t)gw * HD + c0) = o;
    } else {
        float2 o = make_float2(outv[0], outv[1]);
        *reinterpret_cast<float2*>(out + (size_t)gw * HD + c0) = o;
    }
}

// ---------------- launcher ----------------
extern "C" void kernel_launch(void* const* d_in, const int* in_sizes, int n_in,
                              void* d_out, int out_size)
{
    const float* input = (const float*)d_in[0];
    const int*   src   = (const int*)  d_in[1];
    const int*   dst   = (const int*)  d_in[2];
    const float* W1    = (const float*)d_in[3];
    const float* al1   = (const float*)d_in[4];
    const float* ar1   = (const float*)d_in[5];
    const float* b1    = (const float*)d_in[6];
    const float* W2    = (const float*)d_in[7];
    const float* al2   = (const float*)d_in[8];
    const float* ar2   = (const float*)d_in[9];
    const float* b2    = (const float*)d_in[10];
    const float* W3    = (const float*)d_in[11];
    const float* al3   = (const float*)d_in[12];
    const float* ar3   = (const float*)d_in[13];
    const float* b3    = (const float*)d_in[14];
    float* out = (float*)d_out;

    // resolve device-global scratch addresses (host API, not a stream op)
    void *ph, *pel, *per, *py1, *py2;
    cudaGetSymbolAddress(&ph,  g_h);
    cudaGetSymbolAddress(&pel, g_el);
    cudaGetSymbolAddress(&per, g_er);
    cudaGetSymbolAddress(&py1, g_y1);
    cudaGetSymbolAddress(&py2, g_y2);
    float* hbuf = (float*)ph;
    float* elb  = (float*)pel;
    float* erb  = (float*)per;
    float* y1   = (float*)py1;
    float* y2   = (float*)py2;

    // CSR build (edges identical across batches/layers -> build once per launch)
    zero_deg_kernel<<<(NN + 255) / 256, 256>>>();
    hist_kernel<<<(EE + 255) / 256, 256>>>(dst);
    scan_kernel<<<1, 1024>>>();
    scatter_kernel<<<(EE + 255) / 256, 256>>>(src, dst);

    const int gemm_blocks = (NN + 3) / 4;
    const int agg_blocks  = (NN * 32 + 255) / 256;

    for (int b = 0; b < BB; b++) {
        const float* xb = input + (size_t)b * NN * DIN;
        float*       ob = out   + (size_t)b * NN * DOUTC;

        // Layer 1: GATConv(64 -> 2 heads x 64), no activation
        gemm_att_kernel<64, 128, 2><<<gemm_blocks, 128>>>(xb, W1, al1, ar1, hbuf, elb, erb);
        aggregate_kernel<128, 2, false><<<agg_blocks, 256>>>(hbuf, elb, erb, b1, y1);

        // Layer 2: GATConv(128 -> 128, 1 head), ReLU
        gemm_att_kernel<128, 128, 1><<<gemm_blocks, 128>>>(y1, W2, al2, ar2, hbuf, elb, erb);
        aggregate_kernel<128, 1, true><<<agg_blocks, 256>>>(hbuf, elb, erb, b2, y2);

        // Layer 3: GATConv(128 -> 64, 1 head), no activation
        gemm_att_kernel<128, 64, 1><<<gemm_blocks, 128>>>(y2, W3, al3, ar3, hbuf, elb, erb);
        aggregate_kernel<64, 1, false><<<agg_blocks, 256>>>(hbuf, elb, erb, b3, ob);
    }
}

// round 2
// speedup vs baseline: 1.2212x; 1.2212x over previous
#include <cuda_runtime.h>
#include <math.h>

// Problem constants
#define NN    50000
#define EE    800000
#define DIN   64
#define HIDD  128
#define DOUTC 64
#define BB    2

// ---------------- scratch (static device globals; no allocation) ----------------
__device__ float g_h [BB * NN * 128];   // projected features for current layer
__device__ float g_el[BB * NN * 2];     // per-node attention left  (max 2 heads)
__device__ float g_er[BB * NN * 2];     // per-node attention right
__device__ float g_y1[BB * NN * 128];   // layer1 output
__device__ float g_y2[BB * NN * 128];   // layer2 output
__device__ int   g_rowptr[NN + 1];      // CSR by dst
__device__ int   g_cursor[NN];          // degree / scatter cursor
__device__ int   g_csrc [EE];           // src per CSR slot

// ---------------- packed fp32x2 helpers ----------------
__device__ __forceinline__ void fma2(unsigned long long& d,
                                     unsigned long long a,
                                     unsigned long long b) {
    asm("fma.rn.f32x2 %0, %1, %2, %0;" : "+l"(d) : "l"(a), "l"(b));
}
__device__ __forceinline__ float2 up2(unsigned long long v) {
    float2 r;
    asm("mov.b64 {%0, %1}, %2;" : "=f"(r.x), "=f"(r.y) : "l"(v));
    return r;
}

// ---------------- CSR build ----------------
__global__ void zero_deg_kernel() {
    int i = blockIdx.x * blockDim.x + threadIdx.x;
    if (i < NN) g_cursor[i] = 0;
}

__global__ void hist_kernel(const int* __restrict__ dst) {
    int e = blockIdx.x * blockDim.x + threadIdx.x;
    if (e < EE) atomicAdd(&g_cursor[dst[e]], 1);
}

__global__ void scan_kernel() {
    __shared__ int ss[1024];
    const int t  = threadIdx.x;
    const int CH = (NN + 1023) / 1024;
    const int b  = t * CH;
    const int e  = min(b + CH, NN);
    int s = 0;
    for (int i = b; i < e; i++) s += g_cursor[i];
    ss[t] = s;
    __syncthreads();
    for (int off = 1; off < 1024; off <<= 1) {
        int v = (t >= off) ? ss[t - off] : 0;
        __syncthreads();
        ss[t] += v;
        __syncthreads();
    }
    int run = (t == 0) ? 0 : ss[t - 1];
    for (int i = b; i < e; i++) {
        int d = g_cursor[i];
        g_rowptr[i] = run;
        g_cursor[i] = run;
        run += d;
    }
    if (t == 1023) g_rowptr[NN] = ss[1023];
}

__global__ void scatter_kernel(const int* __restrict__ src, const int* __restrict__ dst) {
    int e = blockIdx.x * blockDim.x + threadIdx.x;
    if (e < EE) {
        int p = atomicAdd(&g_cursor[dst[e]], 1);
        g_csrc[p] = src[e];
    }
}

// ---------------- tiled GEMM (f32x2) + attention coefficients ----------------
// Block: 256 threads, tile TM=64 rows x HD cols, K-chunks of 16.
// W is stored duplicated in shared ([w,w] pairs) so packed FMA operands load
// directly as ulonglong2. Each thread owns RT rows x 4 cols.
// blockIdx.y = batch. Computes h = x@W, el = (h*al).sum per head, er likewise.
template <int K, int HD, int H>
__global__ __launch_bounds__(256) void gemm_att_kernel(
    const float* __restrict__ xbase, size_t xstride,
    const float* __restrict__ W,
    const float* __restrict__ al, const float* __restrict__ ar,
    float* __restrict__ hbase, float* __restrict__ elbase, float* __restrict__ erbase)
{
    constexpr int TM  = 64;
    constexpr int KC  = 16;
    constexpr int CG  = HD / 4;            // col-groups (32 or 16)
    constexpr int RT  = TM / (256 / CG);   // rows per thread (8 or 4)
    constexpr int NP  = RT / 2;            // row pairs
    constexpr int D   = HD / H;
    constexpr int LPHW = (CG / H) < 32 ? (CG / H) : 32;  // lanes per head in warp
    constexpr int WITER = (KC * HD / 4 + 255) / 256;     // W float4s per thread

    __shared__ __align__(16) float xs [KC][TM + 4];  // x tile, transposed
    __shared__ __align__(16) float ws2[KC][2 * HD];  // W tile, each value duplicated

    const float* x    = xbase  + (size_t)blockIdx.y * xstride;
    float*       hout = hbase  + (size_t)blockIdx.y * NN * HD;
    float*       el   = elbase + (size_t)blockIdx.y * NN * H;
    float*       er   = erbase + (size_t)blockIdx.y * NN * H;

    const int tid  = threadIdx.x;
    const int lane = tid & 31;
    const int cg   = tid % CG;
    const int rg   = tid / CG;
    const int c0   = cg * 4;
    const int rb   = rg * RT;
    const int row0 = blockIdx.x * TM;

    unsigned long long acc[NP][4];
    #pragma unroll
    for (int p = 0; p < NP; p++)
        #pragma unroll
        for (int c = 0; c < 4; c++) acc[p][c] = 0ull;

    // x tile loader mapping: one float4 per thread per chunk
    const int lr = tid >> 2;                 // 0..63 tile row
    const int lj = tid & 3;                  // float4 slot within 16 k's
    const int lrow = min(row0 + lr, NN - 1); // clamp (safe read, store guarded)
    const float4* xrow = reinterpret_cast<const float4*>(x + (size_t)lrow * K);

    for (int kc = 0; kc < K; kc += KC) {
        // ---- load x tile (transposed) ----
        float4 xv = xrow[(kc >> 2) + lj];
        xs[lj * 4 + 0][lr] = xv.x;
        xs[lj * 4 + 1][lr] = xv.y;
        xs[lj * 4 + 2][lr] = xv.z;
        xs[lj * 4 + 3][lr] = xv.w;
        // ---- load W tile, duplicated ----
        #pragma unroll
        for (int it = 0; it < WITER; it++) {
            int fi = tid + it * 256;
            if (fi < KC * HD / 4) {
                int k  = fi / (HD / 4);
                int cq = fi % (HD / 4);
                float4 wv = *reinterpret_cast<const float4*>(W + (size_t)(kc + k) * HD + cq * 4);
                *reinterpret_cast<float4*>(&ws2[k][cq * 8])     = make_float4(wv.x, wv.x, wv.y, wv.y);
                *reinterpret_cast<float4*>(&ws2[k][cq * 8 + 4]) = make_float4(wv.z, wv.z, wv.w, wv.w);
            }
        }
        __syncthreads();

        #pragma unroll
        for (int k = 0; k < KC; k++) {
            ulonglong2 wa = *reinterpret_cast<const ulonglong2*>(&ws2[k][2 * c0]);
            ulonglong2 wb = *reinterpret_cast<const ulonglong2*>(&ws2[k][2 * c0 + 4]);
            ulonglong2 xa = *reinterpret_cast<const ulonglong2*>(&xs[k][rb]);
            fma2(acc[0][0], xa.x, wa.x);
            fma2(acc[0][1], xa.x, wa.y);
            fma2(acc[0][2], xa.x, wb.x);
            fma2(acc[0][3], xa.x, wb.y);
            fma2(acc[1][0], xa.y, wa.x);
            fma2(acc[1][1], xa.y, wa.y);
            fma2(acc[1][2], xa.y, wb.x);
            fma2(acc[1][3], xa.y, wb.y);
            if constexpr (NP == 4) {
                ulonglong2 xb = *reinterpret_cast<const ulonglong2*>(&xs[k][rb + 4]);
                fma2(acc[2][0], xb.x, wa.x);
                fma2(acc[2][1], xb.x, wa.y);
                fma2(acc[2][2], xb.x, wb.x);
                fma2(acc[2][3], xb.x, wb.y);
                fma2(acc[3][0], xb.y, wa.x);
                fma2(acc[3][1], xb.y, wa.y);
                fma2(acc[3][2], xb.y, wb.x);
                fma2(acc[3][3], xb.y, wb.y);
            }
        }
        __syncthreads();
    }

    // ---- unpack ----
    float vals[RT][4];
    #pragma unroll
    for (int p = 0; p < NP; p++)
        #pragma unroll
        for (int c = 0; c < 4; c++) {
            float2 f = up2(acc[p][c]);
            vals[p * 2 + 0][c] = f.x;
            vals[p * 2 + 1][c] = f.y;
        }

    // ---- store h ----
    #pragma unroll
    for (int i = 0; i < RT; i++) {
        int row = row0 + rb + i;
        if (row < NN)
            *reinterpret_cast<float4*>(hout + (size_t)row * HD + c0) =
                make_float4(vals[i][0], vals[i][1], vals[i][2], vals[i][3]);
    }

    // ---- el / er via warp reduction across col-groups ----
    float al4[4], ar4[4];
    #pragma unroll
    for (int c = 0; c < 4; c++) { al4[c] = al[c0 + c]; ar4[c] = ar[c0 + c]; }
    const int hh = c0 / D;

    #pragma unroll
    for (int i = 0; i < RT; i++) {
        float pel = 0.f, per_ = 0.f;
        #pragma unroll
        for (int c = 0; c < 4; c++) {
            pel  = fmaf(vals[i][c], al4[c], pel);
            per_ = fmaf(vals[i][c], ar4[c], per_);
        }
        #pragma unroll
        for (int off = LPHW >> 1; off > 0; off >>= 1) {
            pel  += __shfl_xor_sync(0xffffffffu, pel,  off);
            per_ += __shfl_xor_sync(0xffffffffu, per_, off);
        }
        int row = row0 + rb + i;
        if ((lane & (LPHW - 1)) == 0 && row < NN) {
            el[row * H + hh] = pel;
            er[row * H + hh] = per_;
        }
    }
}

// ---------------- fused edge-softmax + aggregation ----------------
// One warp per destination node, blockIdx.y = batch. 2-edge software pipeline.
template <int HD, int H, bool RELU>
__global__ __launch_bounds__(256) void aggregate_kernel(
    const float* __restrict__ hbase, const float* __restrict__ elbase,
    const float* __restrict__ erbase, const float* __restrict__ bias,
    float* __restrict__ outbase, size_t outstride)
{
    constexpr int VW = HD / 32;
    constexpr int D  = HD / H;

    const float* hbuf = hbase  + (size_t)blockIdx.y * NN * HD;
    const float* el   = elbase + (size_t)blockIdx.y * NN * H;
    const float* er   = erbase + (size_t)blockIdx.y * NN * H;
    float*       out  = outbase + (size_t)blockIdx.y * outstride;

    const int gw   = (blockIdx.x * blockDim.x + threadIdx.x) >> 5;
    const int lane = threadIdx.x & 31;
    if (gw >= NN) return;

    const int s0 = g_rowptr[gw];
    const int s1 = g_rowptr[gw + 1];
    const int c0 = lane * VW;
    const int hl = c0 / D;

    const float er_own = er[gw * H + hl];

    float acc[VW];
    #pragma unroll
    for (int j = 0; j < VW; j++) acc[j] = 0.f;
    float ssum = 0.f;

    int e = s0;
    for (; e + 1 < s1; e += 2) {
        const int srcA = g_csrc[e];
        const int srcB = g_csrc[e + 1];
        const float elA = el[srcA * H + hl];
        const float elB = el[srcB * H + hl];
        const float* hA = hbuf + (size_t)srcA * HD + c0;
        const float* hB = hbuf + (size_t)srcB * HD + c0;

        float vA = elA + er_own;  vA = (vA > 0.f) ? vA : 0.2f * vA;
        float vB = elB + er_own;  vB = (vB > 0.f) ? vB : 0.2f * vB;
        const float wA = __expf(vA);
        const float wB = __expf(vB);
        ssum += wA + wB;

        if constexpr (VW == 4) {
            float4 a4 = *reinterpret_cast<const float4*>(hA);
            float4 b4 = *reinterpret_cast<const float4*>(hB);
            acc[0] = fmaf(wA, a4.x, acc[0]); acc[0] = fmaf(wB, b4.x, acc[0]);
            acc[1] = fmaf(wA, a4.y, acc[1]); acc[1] = fmaf(wB, b4.y, acc[1]);
            acc[2] = fmaf(wA, a4.z, acc[2]); acc[2] = fmaf(wB, b4.z, acc[2]);
            acc[3] = fmaf(wA, a4.w, acc[3]); acc[3] = fmaf(wB, b4.w, acc[3]);
        } else {
            float2 a2 = *reinterpret_cast<const float2*>(hA);
            float2 b2 = *reinterpret_cast<const float2*>(hB);
            acc[0] = fmaf(wA, a2.x, acc[0]); acc[0] = fmaf(wB, b2.x, acc[0]);
            acc[1] = fmaf(wA, a2.y, acc[1]); acc[1] = fmaf(wB, b2.y, acc[1]);
        }
    }
    if (e < s1) {
        const int src = g_csrc[e];
        float v = el[src * H + hl] + er_own;
        v = (v > 0.f) ? v : 0.2f * v;
        const float w = __expf(v);
        ssum += w;
        const float* hr = hbuf + (size_t)src * HD + c0;
        if constexpr (VW == 4) {
            float4 hv = *reinterpret_cast<const float4*>(hr);
            acc[0] = fmaf(w, hv.x, acc[0]);
            acc[1] = fmaf(w, hv.y, acc[1]);
            acc[2] = fmaf(w, hv.z, acc[2]);
            acc[3] = fmaf(w, hv.w, acc[3]);
        } else {
            float2 hv = *reinterpret_cast<const float2*>(hr);
            acc[0] = fmaf(w, hv.x, acc[0]);
            acc[1] = fmaf(w, hv.y, acc[1]);
        }
    }

    float outv[VW];
    if (s1 > s0) {
        const float inv = 1.f / ssum;
        #pragma unroll
        for (int j = 0; j < VW; j++) outv[j] = fmaf(acc[j], inv, bias[c0 + j]);
    } else {
        #pragma unroll
        for (int j = 0; j < VW; j++) outv[j] = bias[c0 + j];
    }
    if (RELU) {
        #pragma unroll
        for (int j = 0; j < VW; j++) outv[j] = fmaxf(outv[j], 0.f);
    }

    if constexpr (VW == 4) {
        *reinterpret_cast<float4*>(out + (size_t)gw * HD + c0) =
            make_float4(outv[0], outv[1], outv[2], outv[3]);
    } else {
        *reinterpret_cast<float2*>(out + (size_t)gw * HD + c0) =
            make_float2(outv[0], outv[1]);
    }
}

// ---------------- launcher ----------------
extern "C" void kernel_launch(void* const* d_in, const int* in_sizes, int n_in,
                              void* d_out, int out_size)
{
    const float* input = (const float*)d_in[0];
    const int*   src   = (const int*)  d_in[1];
    const int*   dst   = (const int*)  d_in[2];
    const float* W1    = (const float*)d_in[3];
    const float* al1   = (const float*)d_in[4];
    const float* ar1   = (const float*)d_in[5];
    const float* b1    = (const float*)d_in[6];
    const float* W2    = (const float*)d_in[7];
    const float* al2   = (const float*)d_in[8];
    const float* ar2   = (const float*)d_in[9];
    const float* b2    = (const float*)d_in[10];
    const float* W3    = (const float*)d_in[11];
    const float* al3   = (const float*)d_in[12];
    const float* ar3   = (const float*)d_in[13];
    const float* b3    = (const float*)d_in[14];
    float* out = (float*)d_out;

    void *ph, *pel, *per, *py1, *py2;
    cudaGetSymbolAddress(&ph,  g_h);
    cudaGetSymbolAddress(&pel, g_el);
    cudaGetSymbolAddress(&per, g_er);
    cudaGetSymbolAddress(&py1, g_y1);
    cudaGetSymbolAddress(&py2, g_y2);
    float* hbuf = (float*)ph;
    float* elb  = (float*)pel;
    float* erb  = (float*)per;
    float* y1   = (float*)py1;
    float* y2   = (float*)py2;

    // CSR build (edges identical across batches/layers -> build once per launch)
    zero_deg_kernel<<<(NN + 255) / 256, 256>>>();
    hist_kernel<<<(EE + 255) / 256, 256>>>(dst);
    scan_kernel<<<1, 1024>>>();
    scatter_kernel<<<(EE + 255) / 256, 256>>>(src, dst);

    dim3 ggrid((NN + 63) / 64, BB);
    dim3 agrid((NN * 32 + 255) / 256, BB);

    // Layer 1: GATConv(64 -> 2 heads x 64), no activation
    gemm_att_kernel<64, 128, 2><<<ggrid, 256>>>(input, (size_t)NN * DIN, W1, al1, ar1, hbuf, elb, erb);
    aggregate_kernel<128, 2, false><<<agrid, 256>>>(hbuf, elb, erb, b1, y1, (size_t)NN * 128);

    // Layer 2: GATConv(128 -> 128, 1 head), ReLU
    gemm_att_kernel<128, 128, 1><<<ggrid, 256>>>(y1, (size_t)NN * 128, W2, al2, ar2, hbuf, elb, erb);
    aggregate_kernel<128, 1, true><<<agrid, 256>>>(hbuf, elb, erb, b2, y2, (size_t)NN * 128);

    // Layer 3: GATConv(128 -> 64, 1 head), no activation
    gemm_att_kernel<128, 64, 1><<<ggrid, 256>>>(y2, (size_t)NN * 128, W3, al3, ar3, hbuf, elb, erb);
    aggregate_kernel<64, 1, false><<<agrid, 256>>>(hbuf, elb, erb, b3, out, (size_t)NN * DOUTC);
}

// round 3
// speedup vs baseline: 1.2937x; 1.0594x over previous
#include <cuda_runtime.h>
#include <math.h>

// Problem constants
#define NN    50000
#define EE    800000
#define DIN   64
#define HIDD  128
#define DOUTC 64
#define BB    2

// ---------------- scratch (static device globals; no allocation) ----------------
__device__ float g_h [BB * NN * 128];   // projected features for current layer
__device__ float g_el[BB * NN * 2];     // per-node attention left  (max 2 heads)
__device__ float g_er[BB * NN * 2];     // per-node attention right
__device__ float g_y1[BB * NN * 128];   // layer1 output
__device__ float g_y2[BB * NN * 128];   // layer2 output
__device__ int   g_rowptr[NN + 1];      // CSR by dst
__device__ int   g_cursor[NN];          // degree / scatter cursor
__device__ int   g_csrc [EE];           // src per CSR slot

// ---------------- packed fp32x2 helpers ----------------
__device__ __forceinline__ void fma2(unsigned long long& d,
                                     unsigned long long a,
                                     unsigned long long b) {
    asm("fma.rn.f32x2 %0, %1, %2, %0;" : "+l"(d) : "l"(a), "l"(b));
}
__device__ __forceinline__ float2 up2(unsigned long long v) {
    float2 r;
    asm("mov.b64 {%0, %1}, %2;" : "=f"(r.x), "=f"(r.y) : "l"(v));
    return r;
}

// ---------------- CSR build ----------------
__global__ void zero_deg_kernel() {
    int i = blockIdx.x * blockDim.x + threadIdx.x;
    if (i < NN) g_cursor[i] = 0;
}

__global__ void hist_kernel(const int* __restrict__ dst) {
    int e = blockIdx.x * blockDim.x + threadIdx.x;
    if (e < EE) atomicAdd(&g_cursor[dst[e]], 1);
}

__global__ void scan_kernel() {
    __shared__ int ss[1024];
    const int t  = threadIdx.x;
    const int CH = (NN + 1023) / 1024;
    const int b  = t * CH;
    const int e  = min(b + CH, NN);
    int s = 0;
    for (int i = b; i < e; i++) s += g_cursor[i];
    ss[t] = s;
    __syncthreads();
    for (int off = 1; off < 1024; off <<= 1) {
        int v = (t >= off) ? ss[t - off] : 0;
        __syncthreads();
        ss[t] += v;
        __syncthreads();
    }
    int run = (t == 0) ? 0 : ss[t - 1];
    for (int i = b; i < e; i++) {
        int d = g_cursor[i];
        g_rowptr[i] = run;
        g_cursor[i] = run;
        run += d;
    }
    if (t == 1023) g_rowptr[NN] = ss[1023];
}

__global__ void scatter_kernel(const int* __restrict__ src, const int* __restrict__ dst) {
    int e = blockIdx.x * blockDim.x + threadIdx.x;
    if (e < EE) {
        int p = atomicAdd(&g_cursor[dst[e]], 1);
        g_csrc[p] = src[e];
    }
}

// ---------------- tiled GEMM (f32x2) + attention coefficients ----------------
// Block: 256 threads, tile TM=64 rows x HD cols, K-chunks of 16.
// W stored duplicated in shared so packed FMA operands load as ulonglong2.
// blockIdx.y = batch.
template <int K, int HD, int H>
__global__ __launch_bounds__(256) void gemm_att_kernel(
    const float* __restrict__ xbase, size_t xstride,
    const float* __restrict__ W,
    const float* __restrict__ al, const float* __restrict__ ar,
    float* __restrict__ hbase, float* __restrict__ elbase, float* __restrict__ erbase)
{
    constexpr int TM  = 64;
    constexpr int KC  = 16;
    constexpr int CG  = HD / 4;
    constexpr int RT  = TM / (256 / CG);
    constexpr int NP  = RT / 2;
    constexpr int D   = HD / H;
    constexpr int LPHW = (CG / H) < 32 ? (CG / H) : 32;
    constexpr int WITER = (KC * HD / 4 + 255) / 256;

    __shared__ __align__(16) float xs [KC][TM + 4];
    __shared__ __align__(16) float ws2[KC][2 * HD];

    const float* x    = xbase  + (size_t)blockIdx.y * xstride;
    float*       hout = hbase  + (size_t)blockIdx.y * NN * HD;
    float*       el   = elbase + (size_t)blockIdx.y * NN * H;
    float*       er   = erbase + (size_t)blockIdx.y * NN * H;

    const int tid  = threadIdx.x;
    const int lane = tid & 31;
    const int cg   = tid % CG;
    const int rg   = tid / CG;
    const int c0   = cg * 4;
    const int rb   = rg * RT;
    const int row0 = blockIdx.x * TM;

    unsigned long long acc[NP][4];
    #pragma unroll
    for (int p = 0; p < NP; p++)
        #pragma unroll
        for (int c = 0; c < 4; c++) acc[p][c] = 0ull;

    const int lr = tid >> 2;
    const int lj = tid & 3;
    const int lrow = min(row0 + lr, NN - 1);
    const float4* xrow = reinterpret_cast<const float4*>(x + (size_t)lrow * K);

    for (int kc = 0; kc < K; kc += KC) {
        float4 xv = xrow[(kc >> 2) + lj];
        xs[lj * 4 + 0][lr] = xv.x;
        xs[lj * 4 + 1][lr] = xv.y;
        xs[lj * 4 + 2][lr] = xv.z;
        xs[lj * 4 + 3][lr] = xv.w;
        #pragma unroll
        for (int it = 0; it < WITER; it++) {
            int fi = tid + it * 256;
            if (fi < KC * HD / 4) {
                int k  = fi / (HD / 4);
                int cq = fi % (HD / 4);
                float4 wv = *reinterpret_cast<const float4*>(W + (size_t)(kc + k) * HD + cq * 4);
                *reinterpret_cast<float4*>(&ws2[k][cq * 8])     = make_float4(wv.x, wv.x, wv.y, wv.y);
                *reinterpret_cast<float4*>(&ws2[k][cq * 8 + 4]) = make_float4(wv.z, wv.z, wv.w, wv.w);
            }
        }
        __syncthreads();

        #pragma unroll
        for (int k = 0; k < KC; k++) {
            ulonglong2 wa = *reinterpret_cast<const ulonglong2*>(&ws2[k][2 * c0]);
            ulonglong2 wb = *reinterpret_cast<const ulonglong2*>(&ws2[k][2 * c0 + 4]);
            ulonglong2 xa = *reinterpret_cast<const ulonglong2*>(&xs[k][rb]);
            fma2(acc[0][0], xa.x, wa.x);
            fma2(acc[0][1], xa.x, wa.y);
            fma2(acc[0][2], xa.x, wb.x);
            fma2(acc[0][3], xa.x, wb.y);
            fma2(acc[1][0], xa.y, wa.x);
            fma2(acc[1][1], xa.y, wa.y);
            fma2(acc[1][2], xa.y, wb.x);
            fma2(acc[1][3], xa.y, wb.y);
            if constexpr (NP == 4) {
                ulonglong2 xb = *reinterpret_cast<const ulonglong2*>(&xs[k][rb + 4]);
                fma2(acc[2][0], xb.x, wa.x);
                fma2(acc[2][1], xb.x, wa.y);
                fma2(acc[2][2], xb.x, wb.x);
                fma2(acc[2][3], xb.x, wb.y);
                fma2(acc[3][0], xb.y, wa.x);
                fma2(acc[3][1], xb.y, wa.y);
                fma2(acc[3][2], xb.y, wb.x);
                fma2(acc[3][3], xb.y, wb.y);
            }
        }
        __syncthreads();
    }

    float vals[RT][4];
    #pragma unroll
    for (int p = 0; p < NP; p++)
        #pragma unroll
        for (int c = 0; c < 4; c++) {
            float2 f = up2(acc[p][c]);
            vals[p * 2 + 0][c] = f.x;
            vals[p * 2 + 1][c] = f.y;
        }

    #pragma unroll
    for (int i = 0; i < RT; i++) {
        int row = row0 + rb + i;
        if (row < NN)
            *reinterpret_cast<float4*>(hout + (size_t)row * HD + c0) =
                make_float4(vals[i][0], vals[i][1], vals[i][2], vals[i][3]);
    }

    float al4[4], ar4[4];
    #pragma unroll
    for (int c = 0; c < 4; c++) { al4[c] = al[c0 + c]; ar4[c] = ar[c0 + c]; }
    const int hh = c0 / D;

    #pragma unroll
    for (int i = 0; i < RT; i++) {
        float pel = 0.f, per_ = 0.f;
        #pragma unroll
        for (int c = 0; c < 4; c++) {
            pel  = fmaf(vals[i][c], al4[c], pel);
            per_ = fmaf(vals[i][c], ar4[c], per_);
        }
        #pragma unroll
        for (int off = LPHW >> 1; off > 0; off >>= 1) {
            pel  += __shfl_xor_sync(0xffffffffu, pel,  off);
            per_ += __shfl_xor_sync(0xffffffffu, per_, off);
        }
        int row = row0 + rb + i;
        if ((lane & (LPHW - 1)) == 0 && row < NN) {
            el[row * H + hh] = pel;
            er[row * H + hh] = per_;
        }
    }
}

// ---------------- fused edge-softmax + aggregation, BOTH batches per warp ----
// One warp per destination node. The CSR index walk is shared by both batches;
// each edge iteration issues independent gathers for b=0 and b=1 (MLP~8).
template <int HD, int H, bool RELU>
__global__ __launch_bounds__(256) void aggregate2_kernel(
    const float* __restrict__ hbase, const float* __restrict__ elbase,
    const float* __restrict__ erbase, const float* __restrict__ bias,
    float* __restrict__ outbase, size_t outstride)
{
    constexpr int VW = HD / 32;
    constexpr int D  = HD / H;

    const float* h0  = hbase;
    const float* h1  = hbase  + (size_t)NN * HD;
    const float* el0 = elbase;
    const float* el1 = elbase + (size_t)NN * H;
    const float* er0 = erbase;
    const float* er1 = erbase + (size_t)NN * H;
    float*       o0  = outbase;
    float*       o1  = outbase + outstride;

    const int gw   = (blockIdx.x * blockDim.x + threadIdx.x) >> 5;
    const int lane = threadIdx.x & 31;
    if (gw >= NN) return;

    const int s0 = g_rowptr[gw];
    const int s1 = g_rowptr[gw + 1];
    const int c0 = lane * VW;
    const int hl = c0 / D;

    const float erA = er0[gw * H + hl];
    const float erB = er1[gw * H + hl];

    float acc0[VW], acc1[VW];
    #pragma unroll
    for (int j = 0; j < VW; j++) { acc0[j] = 0.f; acc1[j] = 0.f; }
    float sum0 = 0.f, sum1 = 0.f;

    int e = s0;
    for (; e + 1 < s1; e += 2) {
        const int sA = g_csrc[e];
        const int sB = g_csrc[e + 1];
        // 4 independent el gathers
        const float ea0 = el0[sA * H + hl];
        const float ea1 = el1[sA * H + hl];
        const float eb0 = el0[sB * H + hl];
        const float eb1 = el1[sB * H + hl];
        // 4 independent h row gathers
        const float* pa0 = h0 + (size_t)sA * HD + c0;
        const float* pa1 = h1 + (size_t)sA * HD + c0;
        const float* pb0 = h0 + (size_t)sB * HD + c0;
        const float* pb1 = h1 + (size_t)sB * HD + c0;

        float va0 = ea0 + erA; va0 = (va0 > 0.f) ? va0 : 0.2f * va0;
        float va1 = ea1 + erB; va1 = (va1 > 0.f) ? va1 : 0.2f * va1;
        float vb0 = eb0 + erA; vb0 = (vb0 > 0.f) ? vb0 : 0.2f * vb0;
        float vb1 = eb1 + erB; vb1 = (vb1 > 0.f) ? vb1 : 0.2f * vb1;
        const float wa0 = __expf(va0);
        const float wa1 = __expf(va1);
        const float wb0 = __expf(vb0);
        const float wb1 = __expf(vb1);
        sum0 += wa0 + wb0;
        sum1 += wa1 + wb1;

        if constexpr (VW == 4) {
            float4 A0 = *reinterpret_cast<const float4*>(pa0);
            float4 A1 = *reinterpret_cast<const float4*>(pa1);
            float4 B0 = *reinterpret_cast<const float4*>(pb0);
            float4 B1 = *reinterpret_cast<const float4*>(pb1);
            acc0[0] = fmaf(wa0, A0.x, acc0[0]); acc0[0] = fmaf(wb0, B0.x, acc0[0]);
            acc0[1] = fmaf(wa0, A0.y, acc0[1]); acc0[1] = fmaf(wb0, B0.y, acc0[1]);
            acc0[2] = fmaf(wa0, A0.z, acc0[2]); acc0[2] = fmaf(wb0, B0.z, acc0[2]);
            acc0[3] = fmaf(wa0, A0.w, acc0[3]); acc0[3] = fmaf(wb0, B0.w, acc0[3]);
            acc1[0] = fmaf(wa1, A1.x, acc1[0]); acc1[0] = fmaf(wb1, B1.x, acc1[0]);
            acc1[1] = fmaf(wa1, A1.y, acc1[1]); acc1[1] = fmaf(wb1, B1.y, acc1[1]);
            acc1[2] = fmaf(wa1, A1.z, acc1[2]); acc1[2] = fmaf(wb1, B1.z, acc1[2]);
            acc1[3] = fmaf(wa1, A1.w, acc1[3]); acc1[3] = fmaf(wb1, B1.w, acc1[3]);
        } else {
            float2 A0 = *reinterpret_cast<const float2*>(pa0);
            float2 A1 = *reinterpret_cast<const float2*>(pa1);
            float2 B0 = *reinterpret_cast<const float2*>(pb0);
            float2 B1 = *reinterpret_cast<const float2*>(pb1);
            acc0[0] = fmaf(wa0, A0.x, acc0[0]); acc0[0] = fmaf(wb0, B0.x, acc0[0]);
            acc0[1] = fmaf(wa0, A0.y, acc0[1]); acc0[1] = fmaf(wb0, B0.y, acc0[1]);
            acc1[0] = fmaf(wa1, A1.x, acc1[0]); acc1[0] = fmaf(wb1, B1.x, acc1[0]);
            acc1[1] = fmaf(wa1, A1.y, acc1[1]); acc1[1] = fmaf(wb1, B1.y, acc1[1]);
        }
    }
    if (e < s1) {
        const int sA = g_csrc[e];
        const float ea0 = el0[sA * H + hl];
        const float ea1 = el1[sA * H + hl];
        float va0 = ea0 + erA; va0 = (va0 > 0.f) ? va0 : 0.2f * va0;
        float va1 = ea1 + erB; va1 = (va1 > 0.f) ? va1 : 0.2f * va1;
        const float wa0 = __expf(va0);
        const float wa1 = __expf(va1);
        sum0 += wa0;
        sum1 += wa1;
        const float* pa0 = h0 + (size_t)sA * HD + c0;
        const float* pa1 = h1 + (size_t)sA * HD + c0;
        if constexpr (VW == 4) {
            float4 A0 = *reinterpret_cast<const float4*>(pa0);
            float4 A1 = *reinterpret_cast<const float4*>(pa1);
            acc0[0] = fmaf(wa0, A0.x, acc0[0]);
            acc0[1] = fmaf(wa0, A0.y, acc0[1]);
            acc0[2] = fmaf(wa0, A0.z, acc0[2]);
            acc0[3] = fmaf(wa0, A0.w, acc0[3]);
            acc1[0] = fmaf(wa1, A1.x, acc1[0]);
            acc1[1] = fmaf(wa1, A1.y, acc1[1]);
            acc1[2] = fmaf(wa1, A1.z, acc1[2]);
            acc1[3] = fmaf(wa1, A1.w, acc1[3]);
        } else {
            float2 A0 = *reinterpret_cast<const float2*>(pa0);
            float2 A1 = *reinterpret_cast<const float2*>(pa1);
            acc0[0] = fmaf(wa0, A0.x, acc0[0]);
            acc0[1] = fmaf(wa0, A0.y, acc0[1]);
            acc1[0] = fmaf(wa1, A1.x, acc1[0]);
            acc1[1] = fmaf(wa1, A1.y, acc1[1]);
        }
    }

    float bv[VW];
    #pragma unroll
    for (int j = 0; j < VW; j++) bv[j] = bias[c0 + j];

    float out0[VW], out1[VW];
    if (s1 > s0) {
        const float i0 = 1.f / sum0;
        const float i1 = 1.f / sum1;
        #pragma unroll
        for (int j = 0; j < VW; j++) {
            out0[j] = fmaf(acc0[j], i0, bv[j]);
            out1[j] = fmaf(acc1[j], i1, bv[j]);
        }
    } else {
        #pragma unroll
        for (int j = 0; j < VW; j++) { out0[j] = bv[j]; out1[j] = bv[j]; }
    }
    if (RELU) {
        #pragma unroll
        for (int j = 0; j < VW; j++) {
            out0[j] = fmaxf(out0[j], 0.f);
            out1[j] = fmaxf(out1[j], 0.f);
        }
    }

    if constexpr (VW == 4) {
        *reinterpret_cast<float4*>(o0 + (size_t)gw * HD + c0) =
            make_float4(out0[0], out0[1], out0[2], out0[3]);
        *reinterpret_cast<float4*>(o1 + (size_t)gw * HD + c0) =
            make_float4(out1[0], out1[1], out1[2], out1[3]);
    } else {
        *reinterpret_cast<float2*>(o0 + (size_t)gw * HD + c0) =
            make_float2(out0[0], out0[1]);
        *reinterpret_cast<float2*>(o1 + (size_t)gw * HD + c0) =
            make_float2(out1[0], out1[1]);
    }
}

// ---------------- launcher ----------------
extern "C" void kernel_launch(void* const* d_in, const int* in_sizes, int n_in,
                              void* d_out, int out_size)
{
    const float* input = (const float*)d_in[0];
    const int*   src   = (const int*)  d_in[1];
    const int*   dst   = (const int*)  d_in[2];
    const float* W1    = (const float*)d_in[3];
    const float* al1   = (const float*)d_in[4];
    const float* ar1   = (const float*)d_in[5];
    const float* b1    = (const float*)d_in[6];
    const float* W2    = (const float*)d_in[7];
    const float* al2   = (const float*)d_in[8];
    const float* ar2   = (const float*)d_in[9];
    const float* b2    = (const float*)d_in[10];
    const float* W3    = (const float*)d_in[11];
    const float* al3   = (const float*)d_in[12];
    const float* ar3   = (const float*)d_in[13];
    const float* b3    = (const float*)d_in[14];
    float* out = (float*)d_out;

    void *ph, *pel, *per, *py1, *py2;
    cudaGetSymbolAddress(&ph,  g_h);
    cudaGetSymbolAddress(&pel, g_el);
    cudaGetSymbolAddress(&per, g_er);
    cudaGetSymbolAddress(&py1, g_y1);
    cudaGetSymbolAddress(&py2, g_y2);
    float* hbuf = (float*)ph;
    float* elb  = (float*)pel;
    float* erb  = (float*)per;
    float* y1   = (float*)py1;
    float* y2   = (float*)py2;

    // CSR build (edges identical across batches/layers -> build once per launch)
    zero_deg_kernel<<<(NN + 255) / 256, 256>>>();
    hist_kernel<<<(EE + 255) / 256, 256>>>(dst);
    scan_kernel<<<1, 1024>>>();
    scatter_kernel<<<(EE + 255) / 256, 256>>>(src, dst);

    dim3 ggrid((NN + 63) / 64, BB);
    const int agrid = (NN * 32 + 255) / 256;

    // Layer 1: GATConv(64 -> 2 heads x 64)
    gemm_att_kernel<64, 128, 2><<<ggrid, 256>>>(input, (size_t)NN * DIN, W1, al1, ar1, hbuf, elb, erb);
    aggregate2_kernel<128, 2, false><<<agrid, 256>>>(hbuf, elb, erb, b1, y1, (size_t)NN * 128);

    // Layer 2: GATConv(128 -> 128, 1 head), ReLU
    gemm_att_kernel<128, 128, 1><<<ggrid, 256>>>(y1, (size_t)NN * 128, W2, al2, ar2, hbuf, elb, erb);
    aggregate2_kernel<128, 1, true><<<agrid, 256>>>(hbuf, elb, erb, b2, y2, (size_t)NN * 128);

    // Layer 3: GATConv(128 -> 64, 1 head)
    gemm_att_kernel<128, 64, 1><<<ggrid, 256>>>(y2, (size_t)NN * 128, W3, al3, ar3, hbuf, elb, erb);
    aggregate2_kernel<64, 1, false><<<agrid, 256>>>(hbuf, elb, erb, b3, out, (size_t)NN * DOUTC);
}